// round 12
// baseline (speedup 1.0000x reference)
#include <cuda_runtime.h>
#include <cstdint>

// GraphSage 2-layer, tf32 tensor-core (mma.sync m16n8k8), templated on BM.
// out[b][o] = relu( sum_k comb[b][k]*W[o][k] ), comb = [self | mean of 10 neigh]
// BM=32 for layer 1 (68 KB smem -> 3 blocks/SM) with single-row gather
// iterations (low register pressure, no spills under launch_bounds(256,3)).

#define DD     128
#define KN     10
#define B1_SZ  40960
#define B2_SZ  4096

#define KT     64      // W k-tile
#define CPAD   260     // comb row stride (floats); 260%32==4 -> conflict-free frags
#define WPAD   68      // Wsh row stride (floats);  68%32==4  -> conflict-free frags

__device__ float g_h1[B1_SZ * DD];       // layer-1 hidden table (21 MB)

__device__ __forceinline__ uint32_t f2tf32(float f) {
    uint32_t u;
    asm("cvt.rna.tf32.f32 %0, %1;" : "=r"(u) : "f"(f));
    return u;
}

__device__ __forceinline__ float4 add4(float4 a, float4 b) {
    return make_float4(a.x + b.x, a.y + b.y, a.z + b.z, a.w + b.w);
}

__device__ __forceinline__ void mma_tf32(float& c0, float& c1, float& c2, float& c3,
                                         uint32_t a0, uint32_t a1, uint32_t a2, uint32_t a3,
                                         uint32_t b0, uint32_t b1) {
    asm volatile(
        "mma.sync.aligned.m16n8k8.row.col.f32.tf32.tf32.f32 "
        "{%0,%1,%2,%3}, {%4,%5,%6,%7}, {%8,%9}, {%0,%1,%2,%3};\n"
        : "+f"(c0), "+f"(c1), "+f"(c2), "+f"(c3)
        : "r"(a0), "r"(a1), "r"(a2), "r"(a3), "r"(b0), "r"(b1));
}

// Stage W[:, kt:kt+64] (fp32 in GMEM) as tf32 into Wsh[n][k]. CVTs hide under LDG.
__device__ __forceinline__ void stage_w(const float* __restrict__ W, float* Wsh,
                                        int kt, int tid) {
    #pragma unroll
    for (int it = 0; it < 8; it++) {
        const int e  = tid + it * 256;        // 0..2047
        const int n  = e >> 4;                // 0..127
        const int c4 = e & 15;                // float4 idx within k-tile
        float4 wv = __ldg(((const float4*)W) + n * 64 + (kt >> 2) + c4);
        uint4 wt = make_uint4(f2tf32(wv.x), f2tf32(wv.y), f2tf32(wv.z), f2tf32(wv.w));
        *((uint4*)(Wsh + n * WPAD + c4 * 4)) = wt;
    }
}

template <int BM_>
__global__ __launch_bounds__(256, 3)
void sage_tf32(const float* __restrict__ table,   // [T][128]
               const float* __restrict__ W,       // [128][256] fp32
               const int*   __restrict__ nodes,   // [B]
               const int*   __restrict__ neigh,   // [B][10]
               float*       __restrict__ out)     // [B][128]
{
    constexpr int R    = BM_ / 8;          // rows per warp (phase 1)
    constexpr int NM   = BM_ / 16;         // 16-row m-tiles
    constexpr int NCOL = 128 / (8 / NM);   // output cols per warp
    constexpr int NT   = NCOL / 8;         // n-subtiles per warp

    extern __shared__ __align__(16) float smem[];
    float* comb = smem;                    // [BM_][CPAD]
    float* Wsh  = smem + BM_ * CPAD;       // [128][WPAD]

    const int tid  = threadIdx.x;
    const int warp = tid >> 5;
    const int lane = tid & 31;
    const int b0   = blockIdx.x * BM_;

    // stage W k-tile 0 (independent of comb; overlaps with gathers)
    stage_w(W, Wsh, 0, tid);

    // ================= Phase 1: gather + mean -> tf32 comb =================
    // One row per iteration: 11 indices into registers, then 11 independent
    // 512B row gathers in flight; tree-reduce. Low register footprint.
    #pragma unroll
    for (int i = 0; i < R; i++) {
        const int r   = warp * R + i;
        const int row = b0 + r;
        const int node = __ldg(nodes + row);
        int idx[KN];
        #pragma unroll
        for (int k = 0; k < KN; k++) idx[k] = __ldg(neigh + row * KN + k);

        float4 v = __ldg(((const float4*)table) + (long long)node * 32 + lane);
        float4 t[KN];
        #pragma unroll
        for (int k = 0; k < KN; k++)
            t[k] = __ldg(((const float4*)table) + (long long)idx[k] * 32 + lane);

        float4 s4 = add4(add4(add4(t[0], t[1]), add4(t[2], t[3])),
                         add4(add4(t[4], t[5]), add4(t[6], t[7])));
        s4 = add4(s4, add4(t[8], t[9]));

        const float s = 1.0f / (float)KN;
        uint4 sv = make_uint4(f2tf32(v.x), f2tf32(v.y), f2tf32(v.z), f2tf32(v.w));
        uint4 av = make_uint4(f2tf32(s4.x * s), f2tf32(s4.y * s),
                              f2tf32(s4.z * s), f2tf32(s4.w * s));
        ((uint4*)(comb + r * CPAD))[lane]      = sv;   // self [0..127]
        ((uint4*)(comb + r * CPAD + DD))[lane] = av;   // agg  [128..255]
    }
    __syncthreads();

    // ================= Phase 2: tensor-core GEMM =================
    const int g     = lane >> 2;
    const int tig   = lane & 3;
    const int mbase = (warp % NM) * 16;
    const int nbase = (warp / NM) * NCOL;

    float acc[NT][4];
    #pragma unroll
    for (int nt = 0; nt < NT; nt++)
        #pragma unroll
        for (int j = 0; j < 4; j++) acc[nt][j] = 0.f;

    #pragma unroll
    for (int tix = 0; tix < (2 * DD) / KT; tix++) {
        const int kt = tix * KT;
        #pragma unroll
        for (int k0 = 0; k0 < KT; k0 += 8) {
            const uint32_t* ap = (const uint32_t*)(comb + (mbase + g) * CPAD + kt + k0 + tig);
            uint32_t a0 = ap[0];
            uint32_t a1 = ap[8 * CPAD];
            uint32_t a2 = ap[4];
            uint32_t a3 = ap[8 * CPAD + 4];
            #pragma unroll
            for (int nt = 0; nt < NT; nt++) {
                const uint32_t* bp = (const uint32_t*)(Wsh + (nbase + nt * 8 + g) * WPAD + k0 + tig);
                mma_tf32(acc[nt][0], acc[nt][1], acc[nt][2], acc[nt][3],
                         a0, a1, a2, a3, bp[0], bp[4]);
            }
        }
        if (tix < (2 * DD) / KT - 1) {
            __syncthreads();               // all warps done reading Wsh
            stage_w(W, Wsh, kt + KT, tid);
            __syncthreads();               // Wsh tile ready
        }
    }

    // ================= Epilogue: ReLU + store =================
    #pragma unroll
    for (int nt = 0; nt < NT; nt++) {
        const int row = b0 + mbase + g;
        const int col = nbase + nt * 8 + 2 * tig;
        float2 v0 = make_float2(fmaxf(acc[nt][0], 0.f), fmaxf(acc[nt][1], 0.f));
        float2 v1 = make_float2(fmaxf(acc[nt][2], 0.f), fmaxf(acc[nt][3], 0.f));
        *(float2*)(out + (long long)row * DD + col)       = v0;
        *(float2*)(out + (long long)(row + 8) * DD + col) = v1;
    }
}

extern "C" void kernel_launch(void* const* d_in, const int* in_sizes, int n_in,
                              void* d_out, int out_size)
{
    const float* raw    = (const float*)d_in[0];
    const float* W1     = (const float*)d_in[1];
    const float* W2     = (const float*)d_in[2];
    const int*   nodes1 = (const int*)  d_in[3];
    const int*   neigh1 = (const int*)  d_in[4];
    const int*   nodes2 = (const int*)  d_in[5];
    const int*   neigh2 = (const int*)  d_in[6];
    float*       out    = (float*)d_out;

    float* h1 = nullptr;
    cudaGetSymbolAddress((void**)&h1, g_h1);

    const int smem32 = (32 * CPAD + DD * WPAD) * (int)sizeof(float);  // 68,096 B
    const int smem16 = (16 * CPAD + DD * WPAD) * (int)sizeof(float);  // 51,456 B

    static bool attr_done = false;
    if (!attr_done) {
        cudaFuncSetAttribute(sage_tf32<32>,
                             cudaFuncAttributeMaxDynamicSharedMemorySize, smem32);
        cudaFuncSetAttribute(sage_tf32<16>,
                             cudaFuncAttributeMaxDynamicSharedMemorySize, smem16);
        attr_done = true;
    }

    sage_tf32<32><<<B1_SZ / 32, 256, smem32>>>(raw, W1, nodes1, neigh1, h1);
    sage_tf32<16><<<B2_SZ / 16, 256, smem16>>>(h1,  W2, nodes2, neigh2, out);
}

// round 13
// speedup vs baseline: 1.0832x; 1.0832x over previous
#include <cuda_runtime.h>
#include <cstdint>

// GraphSage 2-layer, tf32 tensor-core (mma.sync m16n8k8), templated on BM.
// out[b][o] = relu( sum_k comb[b][k]*W[o][k] ), comb = [self | mean of 10 neigh]
// Phase 1 uses cp.async (LDGSTS) gathers into a SMEM staging slot per warp:
// register-free deep MLP (~44 lines in flight per warp, ~700/SM) to saturate
// the DRAM latency-concurrency product that LDG-register gathers cannot.

#define DD     128
#define KN     10
#define B1_SZ  40960
#define B2_SZ  4096

#define KT     64      // W k-tile
#define CPAD   260     // comb row stride (floats); 260%32==4 -> conflict-free frags
#define WPAD   68      // Wsh row stride (floats);  68%32==4  -> conflict-free frags
#define NCH    (KN + 1)          // chunks per row: self + 10 neighbors
#define SLOT_B (NCH * 512)       // staging bytes per warp slot (5632)

__device__ float g_h1[B1_SZ * DD];       // layer-1 hidden table (21 MB)

__device__ __forceinline__ uint32_t f2tf32(float f) {
    uint32_t u;
    asm("cvt.rna.tf32.f32 %0, %1;" : "=r"(u) : "f"(f));
    return u;
}

__device__ __forceinline__ float4 add4(float4 a, float4 b) {
    return make_float4(a.x + b.x, a.y + b.y, a.z + b.z, a.w + b.w);
}

__device__ __forceinline__ void cp16(uint32_t dst_smem, const void* src) {
    asm volatile("cp.async.cg.shared.global [%0], [%1], 16;"
                 :: "r"(dst_smem), "l"(src));
}
__device__ __forceinline__ void cp_commit() {
    asm volatile("cp.async.commit_group;");
}
__device__ __forceinline__ void cp_wait0() {
    asm volatile("cp.async.wait_group 0;" ::: "memory");
}

__device__ __forceinline__ void mma_tf32(float& c0, float& c1, float& c2, float& c3,
                                         uint32_t a0, uint32_t a1, uint32_t a2, uint32_t a3,
                                         uint32_t b0, uint32_t b1) {
    asm volatile(
        "mma.sync.aligned.m16n8k8.row.col.f32.tf32.tf32.f32 "
        "{%0,%1,%2,%3}, {%4,%5,%6,%7}, {%8,%9}, {%0,%1,%2,%3};\n"
        : "+f"(c0), "+f"(c1), "+f"(c2), "+f"(c3)
        : "r"(a0), "r"(a1), "r"(a2), "r"(a3), "r"(b0), "r"(b1));
}

// Stage W[:, kt:kt+64] (fp32 in GMEM) as tf32 into Wsh[n][k]. CVTs hide under LDG.
__device__ __forceinline__ void stage_w(const float* __restrict__ W, float* Wsh,
                                        int kt, int tid) {
    #pragma unroll
    for (int it = 0; it < 8; it++) {
        const int e  = tid + it * 256;        // 0..2047
        const int n  = e >> 4;                // 0..127
        const int c4 = e & 15;                // float4 idx within k-tile
        float4 wv = __ldg(((const float4*)W) + n * 64 + (kt >> 2) + c4);
        uint4 wt = make_uint4(f2tf32(wv.x), f2tf32(wv.y), f2tf32(wv.z), f2tf32(wv.w));
        *((uint4*)(Wsh + n * WPAD + c4 * 4)) = wt;
    }
}

template <int BM_>
__global__ __launch_bounds__(256, 2)
void sage_tf32(const float* __restrict__ table,   // [T][128]
               const float* __restrict__ W,       // [128][256] fp32
               const int*   __restrict__ nodes,   // [B]
               const int*   __restrict__ neigh,   // [B][10]
               float*       __restrict__ out)     // [B][128]
{
    constexpr int R    = BM_ / 8;          // rows per warp (phase 1)
    constexpr int NM   = BM_ / 16;         // 16-row m-tiles
    constexpr int NCOL = 128 / (8 / NM);   // output cols per warp
    constexpr int NT   = NCOL / 8;         // n-subtiles per warp

    extern __shared__ __align__(16) float smem[];
    float* comb  = smem;                           // [BM_][CPAD]
    float* Wsh   = smem + BM_ * CPAD;              // [128][WPAD]
    float* stage = Wsh + DD * WPAD;                // [8 warps][NCH][128]

    const int tid  = threadIdx.x;
    const int warp = tid >> 5;
    const int lane = tid & 31;
    const int b0   = blockIdx.x * BM_;

    // stage W k-tile 0 (independent of comb; overlaps with gathers)
    stage_w(W, Wsh, 0, tid);

    // ================= Phase 1: cp.async gather + mean -> tf32 comb =========
    {
        float* myStage = stage + warp * (NCH * DD);
        const uint32_t stBase =
            (uint32_t)__cvta_generic_to_shared(myStage) + (uint32_t)(lane * 16);

        // indices for first row
        int idx[NCH];
        {
            const int row = b0 + warp * R;
            idx[0] = __ldg(nodes + row);
            #pragma unroll
            for (int k = 0; k < KN; k++) idx[k + 1] = __ldg(neigh + row * KN + k);
        }

        #pragma unroll
        for (int i = 0; i < R; i++) {
            // issue 11 cp.async chunks for this row (each lane copies its 16B)
            #pragma unroll
            for (int c = 0; c < NCH; c++) {
                const float* src = table + (long long)idx[c] * DD + lane * 4;
                cp16(stBase + c * 512, src);
            }
            cp_commit();

            // prefetch next row's indices while copies are in flight
            int nidx[NCH];
            if (i + 1 < R) {
                const int nrow = b0 + warp * R + i + 1;
                nidx[0] = __ldg(nodes + nrow);
                #pragma unroll
                for (int k = 0; k < KN; k++) nidx[k + 1] = __ldg(neigh + nrow * KN + k);
            }

            cp_wait0();   // this thread's copies done; we read only our own 16B

            // reduce: chunk 0 = self, chunks 1..10 -> mean
            const float4* sp = (const float4*)(myStage) + lane;   // stride 32 float4/chunk
            float4 v  = sp[0];
            float4 s0 = add4(sp[32 * 1], sp[32 * 2]);
            float4 s1 = add4(sp[32 * 3], sp[32 * 4]);
            float4 s2 = add4(sp[32 * 5], sp[32 * 6]);
            float4 s3 = add4(sp[32 * 7], sp[32 * 8]);
            float4 s4 = add4(sp[32 * 9], sp[32 * 10]);
            float4 s  = add4(add4(add4(s0, s1), add4(s2, s3)), s4);

            const float m = 1.0f / (float)KN;
            uint4 sv = make_uint4(f2tf32(v.x), f2tf32(v.y), f2tf32(v.z), f2tf32(v.w));
            uint4 av = make_uint4(f2tf32(s.x * m), f2tf32(s.y * m),
                                  f2tf32(s.z * m), f2tf32(s.w * m));
            const int r = warp * R + i;
            ((uint4*)(comb + r * CPAD))[lane]      = sv;   // self [0..127]
            ((uint4*)(comb + r * CPAD + DD))[lane] = av;   // agg  [128..255]

            if (i + 1 < R) {
                #pragma unroll
                for (int c = 0; c < NCH; c++) idx[c] = nidx[c];
            }
        }
    }
    __syncthreads();

    // ================= Phase 2: tensor-core GEMM =================
    const int g     = lane >> 2;
    const int tig   = lane & 3;
    const int mbase = (warp % NM) * 16;
    const int nbase = (warp / NM) * NCOL;

    float acc[NT][4];
    #pragma unroll
    for (int nt = 0; nt < NT; nt++)
        #pragma unroll
        for (int j = 0; j < 4; j++) acc[nt][j] = 0.f;

    #pragma unroll
    for (int tix = 0; tix < (2 * DD) / KT; tix++) {
        const int kt = tix * KT;
        #pragma unroll
        for (int k0 = 0; k0 < KT; k0 += 8) {
            const uint32_t* ap = (const uint32_t*)(comb + (mbase + g) * CPAD + kt + k0 + tig);
            uint32_t a0 = ap[0];
            uint32_t a1 = ap[8 * CPAD];
            uint32_t a2 = ap[4];
            uint32_t a3 = ap[8 * CPAD + 4];
            #pragma unroll
            for (int nt = 0; nt < NT; nt++) {
                const uint32_t* bp = (const uint32_t*)(Wsh + (nbase + nt * 8 + g) * WPAD + k0 + tig);
                mma_tf32(acc[nt][0], acc[nt][1], acc[nt][2], acc[nt][3],
                         a0, a1, a2, a3, bp[0], bp[4]);
            }
        }
        if (tix < (2 * DD) / KT - 1) {
            __syncthreads();               // all warps done reading Wsh
            stage_w(W, Wsh, kt + KT, tid);
            __syncthreads();               // Wsh tile ready
        }
    }

    // ================= Epilogue: ReLU + store =================
    #pragma unroll
    for (int nt = 0; nt < NT; nt++) {
        const int row = b0 + mbase + g;
        const int col = nbase + nt * 8 + 2 * tig;
        float2 v0 = make_float2(fmaxf(acc[nt][0], 0.f), fmaxf(acc[nt][1], 0.f));
        float2 v1 = make_float2(fmaxf(acc[nt][2], 0.f), fmaxf(acc[nt][3], 0.f));
        *(float2*)(out + (long long)row * DD + col)       = v0;
        *(float2*)(out + (long long)(row + 8) * DD + col) = v1;
    }
}

extern "C" void kernel_launch(void* const* d_in, const int* in_sizes, int n_in,
                              void* d_out, int out_size)
{
    const float* raw    = (const float*)d_in[0];
    const float* W1     = (const float*)d_in[1];
    const float* W2     = (const float*)d_in[2];
    const int*   nodes1 = (const int*)  d_in[3];
    const int*   neigh1 = (const int*)  d_in[4];
    const int*   nodes2 = (const int*)  d_in[5];
    const int*   neigh2 = (const int*)  d_in[6];
    float*       out    = (float*)d_out;

    float* h1 = nullptr;
    cudaGetSymbolAddress((void**)&h1, g_h1);

    const int stageB = 8 * SLOT_B;                                   // 45,056 B
    const int smem32 = (32 * CPAD + DD * WPAD) * (int)sizeof(float) + stageB; // 113,152 B
    const int smem16 = (16 * CPAD + DD * WPAD) * (int)sizeof(float) + stageB; //  96,512 B

    static bool attr_done = false;
    if (!attr_done) {
        cudaFuncSetAttribute(sage_tf32<32>,
                             cudaFuncAttributeMaxDynamicSharedMemorySize, smem32);
        cudaFuncSetAttribute(sage_tf32<16>,
                             cudaFuncAttributeMaxDynamicSharedMemorySize, smem16);
        attr_done = true;
    }

    sage_tf32<32><<<B1_SZ / 32, 256, smem32>>>(raw, W1, nodes1, neigh1, h1);
    sage_tf32<16><<<B2_SZ / 16, 256, smem16>>>(h1,  W2, nodes2, neigh2, out);
}